// round 11
// baseline (speedup 1.0000x reference)
#include <cuda_runtime.h>

// Problem constants
#define Bb   128
#define Tt   256
#define Nn   16
#define Kk   10
#define Hh   20
#define BT   32768          // Bb*Tt
#define KT   (Kk*Tt)        // 2560

typedef unsigned long long u64;

// Scratch (static device globals — no allocation)
// Sample index j = t*128 + b (b-fastest)
__device__ float g_xs[Nn * BT];                    // standardized x, [n][j], 2 MB
__device__ float g_t [(size_t)Kk * Nn * BT];       // t values, [k][n][j], 20 MB
__device__ float g_sq[KT];                         // per-(k,t) squared diffs
__device__ unsigned int g_kt_ctr[Kk * 32];         // per-(k,ty) completion counters
__device__ unsigned int g_tail_ctr;                // tail completion counter

// ---------------- packed f32x2 helpers ----------------
__device__ __forceinline__ u64 pk(float lo, float hi) {
    u64 r; asm("mov.b64 %0,{%1,%2};" : "=l"(r) : "f"(lo), "f"(hi)); return r;
}
__device__ __forceinline__ float2 up(u64 v) {
    float2 f; asm("mov.b64 {%0,%1},%2;" : "=f"(f.x), "=f"(f.y) : "l"(v)); return f;
}
#define FMA2(d,a,b,c) asm("fma.rn.f32x2 %0,%1,%2,%3;" : "=l"(d) : "l"(a), "l"(b), "l"(c))
#define ADD2(d,a,b)   asm("add.rn.f32x2 %0,%1,%2;"    : "=l"(d) : "l"(a), "l"(b))
#define MUL2(d,a,b)   asm("mul.rn.f32x2 %0,%1,%2;"    : "=l"(d) : "l"(a), "l"(b))

__device__ __forceinline__ u64 relu2(u64 v) {
    float2 f = up(v);
    return pk(fmaxf(f.x, 0.f), fmaxf(f.y, 0.f));
}

// ---------------------------------------------------------------------------
// Kernel 1: fused standardize: stats over b (ddof=1) + normalize + transpose
// x[b][t][n] -> g_xs[n][t*128+b]. Block = all 128 b x 2 t x 16 n (16 KB tile).
// Loads: 8 consecutive threads read 128B contiguous. grid = 128, 256 thr.
// ---------------------------------------------------------------------------
__global__ void __launch_bounds__(256) std_kernel(const float* __restrict__ x) {
    __shared__ float s[32][132];       // [n*2+dt][b]
    __shared__ float2 coef[32];        // {ri, -mu*ri}
    int t0 = blockIdx.x * 2;
    int tid = threadIdx.x;

    // load 1024 float4 (4/thread): f -> nq=f&3, dt=(f>>2)&1, b=f>>3
#pragma unroll
    for (int r = 0; r < 4; r++) {
        int f = r * 256 + tid;
        int nq = f & 3, dt = (f >> 2) & 1, b = f >> 3;
        float4 v = *(const float4*)(x + ((size_t)(b * Tt + t0 + dt)) * Nn + nq * 4);
        s[(nq * 4 + 0) * 2 + dt][b] = v.x;
        s[(nq * 4 + 1) * 2 + dt][b] = v.y;
        s[(nq * 4 + 2) * 2 + dt][b] = v.z;
        s[(nq * 4 + 3) * 2 + dt][b] = v.w;
    }
    __syncthreads();

    // stats: 8 threads per column
    int col = tid >> 3, sub = tid & 7;
    float S = 0.f, Q = 0.f;
#pragma unroll
    for (int i = 0; i < 16; i++) {
        float v = s[col][sub * 16 + i];
        S += v; Q = fmaf(v, v, Q);
    }
#pragma unroll
    for (int o = 4; o; o >>= 1) {
        S += __shfl_xor_sync(0xffffffffu, S, o);
        Q += __shfl_xor_sync(0xffffffffu, Q, o);
    }
    if (sub == 0) {
        float mu = S * (1.f / 128.f);
        float ri = 1.f / sqrtf((Q - S * mu) * (1.f / 127.f));   // ddof=1, no eps
        coef[col] = make_float2(ri, -mu * ri);
    }
    __syncthreads();

    // normalized write: 8 threads per column, each 16 b (64B); coalesced
    float2 c = coef[col];
    int n = col >> 1, dt = col & 1;
    float* outp = g_xs + n * BT + (t0 + dt) * 128 + sub * 16;
#pragma unroll
    for (int q = 0; q < 4; q++) {
        float4 o;
        o.x = fmaf(s[col][sub * 16 + q * 4 + 0], c.x, c.y);
        o.y = fmaf(s[col][sub * 16 + q * 4 + 1], c.x, c.y);
        o.z = fmaf(s[col][sub * 16 + q * 4 + 2], c.x, c.y);
        o.w = fmaf(s[col][sub * 16 + q * 4 + 3], c.x, c.y);
        *(float4*)(outp + q * 4) = o;
    }
}

// ---------------------------------------------------------------------------
// Kernel 2: MLP sweep + inline penalty tail.
// Block (kn, ty) covers t in [ty*8, ty*8+8) x all b for one (k,n).
// The 16th-arriving block of each (k,ty) group runs the penalty for its 8 t's
// (L2-hot). The 320th tail reduces g_sq -> out. All counters self-reset.
// grid = (K*N, 32), 128 threads.
// ---------------------------------------------------------------------------
__global__ void __launch_bounds__(128) mlp_kernel(
    const float* __restrict__ W1, const float* __restrict__ b1,
    const float* __restrict__ W2, const float* __restrict__ b2,
    const float* __restrict__ W3, const float* __restrict__ b3,
    float* __restrict__ out)
{
    __shared__ __align__(16) float sw2f[Hh][Hh * 2];   // [o][2i..2i+1] = dup W2[o][i]
    __shared__ __align__(16) float sw1b1[Hh][4];       // {w1,w1,b1,b1}
    __shared__ __align__(16) float sb2w3[Hh][4];       // {b2,b2,w3,w3}
    __shared__ __align__(16) float sc[4];              // {w3sum,w3sum,b3,b3}
    // tail storage
    __shared__ float ts[32][132];
    __shared__ float sac[32][2];
    __shared__ float part[2][2];
    __shared__ float fred[4];
    __shared__ unsigned int s_flag;

    int kn = blockIdx.x;          // k*N + n
    int ty = blockIdx.y;
    int n  = kn & 15;
    int k  = kn >> 4;
    int tid = threadIdx.x;

    for (int idx = tid; idx < Hh * Hh; idx += 128) {
        float v = W2[kn * Hh * Hh + idx];
        int o = idx / Hh, i = idx % Hh;
        sw2f[o][2 * i] = v; sw2f[o][2 * i + 1] = v;
    }
    if (tid < Hh) {
        float w = W1[kn * Hh + tid], b = b1[kn * Hh + tid];
        sw1b1[tid][0] = w; sw1b1[tid][1] = w;
        sw1b1[tid][2] = b; sw1b1[tid][3] = b;
        float bb = b2[kn * Hh + tid];
        float w3 = W3[kn * Hh + tid];
        sb2w3[tid][0] = bb; sb2w3[tid][1] = bb;
        sb2w3[tid][2] = w3; sb2w3[tid][3] = w3;
    }
    if (tid == 0) {
        float s3 = 0.f;
#pragma unroll
        for (int i = 0; i < Hh; i++) s3 += W3[kn * Hh + i];
        sc[0] = s3; sc[1] = s3;
        float bb3 = b3[kn];
        sc[2] = bb3; sc[3] = bb3;
    }
    __syncthreads();

    const float* xs = g_xs + n * BT;
    float* tout = g_t + (size_t)(k * Nn + n) * BT;

    int j0 = (ty * 128 + tid) * 8;
    float4 xa = *(const float4*)(xs + j0);
    float4 xb = *(const float4*)(xs + j0 + 4);
    u64 xp[4];
    xp[0] = pk(xa.x, xa.y); xp[1] = pk(xa.z, xa.w);
    xp[2] = pk(xb.x, xb.y); xp[3] = pk(xb.z, xb.w);

    const u64 ZERO = 0ull;
    const u64 c005  = pk(0.05f, 0.05f);
    const u64 cn005 = pk(-0.05f, -0.05f);

    // ---- layer 1 with streamed LN1 stats ----
    u64 h[4][Hh];
    u64 s1[4], q1[4];
#pragma unroll
    for (int p = 0; p < 4; p++) { s1[p] = ZERO; q1[p] = ZERO; }
#pragma unroll
    for (int i = 0; i < Hh; i++) {
        ulonglong2 wb = *(const ulonglong2*)&sw1b1[i][0];
#pragma unroll
        for (int p = 0; p < 4; p++) {
            u64 t; FMA2(t, xp[p], wb.x, wb.y);
            t = relu2(t);
            h[p][i] = t;
            ADD2(s1[p], s1[p], t);
            FMA2(q1[p], t, t, q1[p]);
        }
    }
    // LN1 in place
#pragma unroll
    for (int p = 0; p < 4; p++) {
        u64 mu, nmu, ex, var;
        MUL2(mu,  s1[p], c005);
        MUL2(nmu, s1[p], cn005);
        MUL2(ex,  q1[p], c005);
        FMA2(var, mu, nmu, ex);     // E[h^2] - mu^2 (biased)
        float2 vf = up(var);
        float rx = rsqrtf(vf.x + 1e-5f);
        float ry = rsqrtf(vf.y + 1e-5f);
        u64 r1 = pk(rx, ry);
        u64 v1; MUL2(v1, nmu, r1);
#pragma unroll
        for (int i = 0; i < Hh; i++)
            FMA2(h[p][i], h[p][i], r1, v1);
    }

    // ---- layer 2; accumulators start at b2; stream LN2 stats + W3 dot ----
    u64 s2[4], q2[4], d3[4];
#pragma unroll
    for (int p = 0; p < 4; p++) { s2[p] = ZERO; q2[p] = ZERO; d3[p] = ZERO; }

#pragma unroll 2
    for (int o = 0; o < Hh; o++) {
        const ulonglong2* wrow = (const ulonglong2*)&sw2f[o][0];
        ulonglong2 bw = *(const ulonglong2*)&sb2w3[o][0];   // {b2 dup, w3 dup}
        u64 a[4];
        a[0] = bw.x; a[1] = bw.x; a[2] = bw.x; a[3] = bw.x;
#pragma unroll
        for (int q = 0; q < Hh / 2; q++) {
            ulonglong2 wv = wrow[q];
#pragma unroll
            for (int p = 0; p < 4; p++) {
                FMA2(a[p], h[p][2 * q],     wv.x, a[p]);
                FMA2(a[p], h[p][2 * q + 1], wv.y, a[p]);
            }
        }
#pragma unroll
        for (int p = 0; p < 4; p++) {
            u64 h2 = relu2(a[p]);
            ADD2(s2[p], s2[p], h2);
            FMA2(q2[p], h2, h2, q2[p]);
            FMA2(d3[p], h2, bw.y, d3[p]);
        }
    }

    // ---- LN2 fold + head ----
    u64 w3s = *(const u64*)&sc[0];
    u64 b3d = *(const u64*)&sc[2];
    float outv[8];
#pragma unroll
    for (int p = 0; p < 4; p++) {
        u64 mu2, nmu2, ex2, var2;
        MUL2(mu2,  s2[p], c005);
        MUL2(nmu2, s2[p], cn005);
        MUL2(ex2,  q2[p], c005);
        FMA2(var2, mu2, nmu2, ex2);
        float2 vf = up(var2);
        float rx = rsqrtf(vf.x + 1e-5f);
        float ry = rsqrtf(vf.y + 1e-5f);
        u64 r2 = pk(rx, ry);
        u64 tmp; FMA2(tmp, nmu2, w3s, d3[p]);
        u64 o2;  FMA2(o2, r2, tmp, b3d);
        float2 of = up(o2);
        outv[2 * p] = of.x; outv[2 * p + 1] = of.y;
    }
    *(float4*)(tout + j0)     = make_float4(outv[0], outv[1], outv[2], outv[3]);
    *(float4*)(tout + j0 + 4) = make_float4(outv[4], outv[5], outv[6], outv[7]);

    // ======================= penalty tail =======================
    __threadfence();
    if (tid == 0) {
        unsigned int old = atomicAdd(&g_kt_ctr[k * 32 + ty], 1u);
        s_flag = (old == 15u) ? 1u : 0u;
    }
    __syncthreads();
    if (!s_flag) return;
    __threadfence();                       // acquire: see peers' g_t writes
    if (tid == 0) g_kt_ctr[k * 32 + ty] = 0u;   // reset for graph replay

    int wid = tid >> 5, lane = tid & 31;

#pragma unroll 1
    for (int tq = 0; tq < 4; tq++) {
        int tt0 = ty * 8 + tq * 2;

        // load: warp-inst = one (n,dt) plane (512B contiguous, L2-hot)
#pragma unroll
        for (int pp = 0; pp < 8; pp++) {
            int plane = pp * 4 + wid;       // = n*2 + dt
            int nn = plane >> 1;
            int dt = plane & 1;
            const float4* src = (const float4*)(g_t +
                ((size_t)(k * 16 + nn)) * BT + (tt0 + dt) * 128);
            float4 v = src[lane];
            *(float4*)&ts[plane][lane * 4] = v;
        }
        __syncthreads();

        // stats: sum + sumsq over b (4 threads per column)
        {
            int col = tid >> 2, sub = tid & 3;
            float S = 0.f, Q = 0.f;
#pragma unroll 8
            for (int i = 0; i < 32; i++) {
                float v = ts[col][sub * 32 + i];
                S += v; Q = fmaf(v, v, Q);
            }
#pragma unroll
            for (int o = 2; o; o >>= 1) {
                S += __shfl_xor_sync(0xffffffffu, S, o);
                Q += __shfl_xor_sync(0xffffffffu, Q, o);
            }
            if (sub == 0) {
                float mu = S * (1.f / 128.f);
                float r  = 1.f / (sqrtf((Q - S * mu) * (1.f / 127.f)) + 1e-8f);
                sac[col][0] = r;
                sac[col][1] = -mu * r;
            }
        }
        __syncthreads();

        // product: warp = (dt, b-half); prod_marginals == 0 in fp32 so
        // d^2 = prod_joint^2.
        {
            int dt = wid >> 1, bh = wid & 1;
            float2 ac[16];
#pragma unroll
            for (int nn = 0; nn < 16; nn++)
                ac[nn] = *(const float2*)&sac[nn * 2 + dt][0];

            float acc = 0.f;
#pragma unroll
            for (int j = 0; j < 2; j++) {
                int bb = bh * 64 + j * 32 + lane;
                float prod = fmaf(ts[0 * 2 + dt][bb], ac[0].x, ac[0].y);
#pragma unroll
                for (int nn = 1; nn < 16; nn++)
                    prod *= fmaf(ts[nn * 2 + dt][bb], ac[nn].x, ac[nn].y);
                acc += prod;
            }
#pragma unroll
            for (int o = 16; o; o >>= 1) acc += __shfl_xor_sync(0xffffffffu, acc, o);
            if (lane == 0) part[dt][bh] = acc;
        }
        __syncthreads();
        if (tid < 2) {
            float pj = (part[tid][0] + part[tid][1]) * (1.f / 128.f);
            g_sq[k * Tt + tt0 + tid] = pj * pj;
        }
        __syncthreads();
    }

    // tail-completion counter: 320th tail reduces g_sq deterministically
    __threadfence();
    if (tid == 0) {
        unsigned int o = atomicAdd(&g_tail_ctr, 1u);
        s_flag = (o == (unsigned int)(Kk * 32 - 1)) ? 1u : 0u;
    }
    __syncthreads();
    if (!s_flag) return;
    __threadfence();

    float facc = 0.f;
    for (int i = tid; i < KT; i += 128) facc += g_sq[i];
#pragma unroll
    for (int o = 16; o; o >>= 1) facc += __shfl_xor_sync(0xffffffffu, facc, o);
    if ((tid & 31) == 0) fred[tid >> 5] = facc;
    __syncthreads();
    if (tid == 0) {
        out[0] = (fred[0] + fred[1] + fred[2] + fred[3]) * (1.f / (float)KT);
        g_tail_ctr = 0u;   // reset for graph replay
    }
}

// ---------------------------------------------------------------------------
extern "C" void kernel_launch(void* const* d_in, const int* in_sizes, int n_in,
                              void* d_out, int out_size) {
    const float* x  = (const float*)d_in[0];
    const float* W1 = (const float*)d_in[1];
    const float* b1 = (const float*)d_in[2];
    const float* W2 = (const float*)d_in[3];
    const float* b2 = (const float*)d_in[4];
    const float* W3 = (const float*)d_in[5];
    const float* b3 = (const float*)d_in[6];

    std_kernel<<<128, 256>>>(x);

    dim3 g2(Kk * Nn, 32);
    mlp_kernel<<<g2, 128>>>(W1, b1, W2, b2, W3, b3, (float*)d_out);
}

// round 12
// speedup vs baseline: 1.1219x; 1.1219x over previous
#include <cuda_runtime.h>

// Problem constants
#define Bb   128
#define Tt   256
#define Nn   16
#define Kk   10
#define Hh   20
#define BT   32768          // Bb*Tt
#define KT   (Kk*Tt)        // 2560

typedef unsigned long long u64;

// Scratch (static device globals — no allocation)
// Sample index j = t*128 + b (b-fastest)
__device__ float g_xs[Nn * BT];                    // standardized x, [n][j], 2 MB
__device__ float g_t [(size_t)Kk * Nn * BT];       // t values, [k][n][j], 20 MB
__device__ float g_sq[KT];                         // per-(k,t) squared diffs
__device__ unsigned int g_ctr;                     // completion counter (zero-init)

// ---------------- packed f32x2 helpers ----------------
__device__ __forceinline__ u64 pk(float lo, float hi) {
    u64 r; asm("mov.b64 %0,{%1,%2};" : "=l"(r) : "f"(lo), "f"(hi)); return r;
}
__device__ __forceinline__ float2 up(u64 v) {
    float2 f; asm("mov.b64 {%0,%1},%2;" : "=f"(f.x), "=f"(f.y) : "l"(v)); return f;
}
#define FMA2(d,a,b,c) asm("fma.rn.f32x2 %0,%1,%2,%3;" : "=l"(d) : "l"(a), "l"(b), "l"(c))
#define ADD2(d,a,b)   asm("add.rn.f32x2 %0,%1,%2;"    : "=l"(d) : "l"(a), "l"(b))
#define MUL2(d,a,b)   asm("mul.rn.f32x2 %0,%1,%2;"    : "=l"(d) : "l"(a), "l"(b))

__device__ __forceinline__ u64 relu2(u64 v) {
    float2 f = up(v);
    return pk(fmaxf(f.x, 0.f), fmaxf(f.y, 0.f));
}

// ---------------------------------------------------------------------------
// Kernel 1: fused standardize: stats over b (ddof=1) + normalize + transpose
// x[b][t][n] -> g_xs[n][t*128+b]. Block = all 128 b x 2 t x 16 n (16 KB tile).
// x read exactly once, coalesced. grid = 128, 256 threads.
// ---------------------------------------------------------------------------
__global__ void __launch_bounds__(256) std_kernel(const float* __restrict__ x) {
    __shared__ float s[32][132];       // [n*2+dt][b]
    __shared__ float2 coef[32];        // {ri, -mu*ri}
    int t0 = blockIdx.x * 2;
    int tid = threadIdx.x;

    // load 1024 float4 (4/thread): f -> nq=f&3, dt=(f>>2)&1, b=f>>3
#pragma unroll
    for (int r = 0; r < 4; r++) {
        int f = r * 256 + tid;
        int nq = f & 3, dt = (f >> 2) & 1, b = f >> 3;
        float4 v = *(const float4*)(x + ((size_t)(b * Tt + t0 + dt)) * Nn + nq * 4);
        s[(nq * 4 + 0) * 2 + dt][b] = v.x;
        s[(nq * 4 + 1) * 2 + dt][b] = v.y;
        s[(nq * 4 + 2) * 2 + dt][b] = v.z;
        s[(nq * 4 + 3) * 2 + dt][b] = v.w;
    }
    __syncthreads();

    // stats: 8 threads per column
    int col = tid >> 3, sub = tid & 7;
    float S = 0.f, Q = 0.f;
#pragma unroll
    for (int i = 0; i < 16; i++) {
        float v = s[col][sub * 16 + i];
        S += v; Q = fmaf(v, v, Q);
    }
#pragma unroll
    for (int o = 4; o; o >>= 1) {
        S += __shfl_xor_sync(0xffffffffu, S, o);
        Q += __shfl_xor_sync(0xffffffffu, Q, o);
    }
    if (sub == 0) {
        float mu = S * (1.f / 128.f);
        float ri = 1.f / sqrtf((Q - S * mu) * (1.f / 127.f));   // ddof=1, no eps
        coef[col] = make_float2(ri, -mu * ri);
    }
    __syncthreads();

    // normalized write: 8 threads per column, each 16 b (64B); coalesced
    float2 c = coef[col];
    int n = col >> 1, dt = col & 1;
    float* outp = g_xs + n * BT + (t0 + dt) * 128 + sub * 16;
#pragma unroll
    for (int q = 0; q < 4; q++) {
        float4 o;
        o.x = fmaf(s[col][sub * 16 + q * 4 + 0], c.x, c.y);
        o.y = fmaf(s[col][sub * 16 + q * 4 + 1], c.x, c.y);
        o.z = fmaf(s[col][sub * 16 + q * 4 + 2], c.x, c.y);
        o.w = fmaf(s[col][sub * 16 + q * 4 + 3], c.x, c.y);
        *(float4*)(outp + q * 4) = o;
    }
}

// ---------------------------------------------------------------------------
// Kernel 2: MLP sweep, packed f32x2, 8 samples per thread (4 packed pairs).
// Block = 128. grid = (K*N, 32). (Proven R9 form, ~95% of FMA2 issue floor.)
// ---------------------------------------------------------------------------
__global__ void __launch_bounds__(128) mlp_kernel(
    const float* __restrict__ W1, const float* __restrict__ b1,
    const float* __restrict__ W2, const float* __restrict__ b2,
    const float* __restrict__ W3, const float* __restrict__ b3)
{
    __shared__ __align__(16) float sw2f[Hh][Hh * 2];   // [o][2i..2i+1] = dup W2[o][i]
    __shared__ __align__(16) float sw1b1[Hh][4];       // {w1,w1,b1,b1}
    __shared__ __align__(16) float sb2w3[Hh][4];       // {b2,b2,w3,w3}
    __shared__ __align__(16) float sc[4];              // {w3sum,w3sum,b3,b3}

    int kn = blockIdx.x;          // k*N + n
    int n  = kn & 15;
    int k  = kn >> 4;
    int tid = threadIdx.x;

    for (int idx = tid; idx < Hh * Hh; idx += 128) {
        float v = W2[kn * Hh * Hh + idx];
        int o = idx / Hh, i = idx % Hh;
        sw2f[o][2 * i] = v; sw2f[o][2 * i + 1] = v;
    }
    if (tid < Hh) {
        float w = W1[kn * Hh + tid], b = b1[kn * Hh + tid];
        sw1b1[tid][0] = w; sw1b1[tid][1] = w;
        sw1b1[tid][2] = b; sw1b1[tid][3] = b;
        float bb = b2[kn * Hh + tid];
        float w3 = W3[kn * Hh + tid];
        sb2w3[tid][0] = bb; sb2w3[tid][1] = bb;
        sb2w3[tid][2] = w3; sb2w3[tid][3] = w3;
    }
    if (tid == 0) {
        float s3 = 0.f;
#pragma unroll
        for (int i = 0; i < Hh; i++) s3 += W3[kn * Hh + i];
        sc[0] = s3; sc[1] = s3;
        float bb3 = b3[kn];
        sc[2] = bb3; sc[3] = bb3;
    }
    __syncthreads();

    const float* xs = g_xs + n * BT;
    float* tout = g_t + (size_t)(k * Nn + n) * BT;

    int j0 = (blockIdx.y * 128 + tid) * 8;
    float4 xa = *(const float4*)(xs + j0);
    float4 xb = *(const float4*)(xs + j0 + 4);
    u64 xp[4];
    xp[0] = pk(xa.x, xa.y); xp[1] = pk(xa.z, xa.w);
    xp[2] = pk(xb.x, xb.y); xp[3] = pk(xb.z, xb.w);

    const u64 ZERO = 0ull;
    const u64 c005  = pk(0.05f, 0.05f);
    const u64 cn005 = pk(-0.05f, -0.05f);

    // ---- layer 1 with streamed LN1 stats ----
    u64 h[4][Hh];
    u64 s1[4], q1[4];
#pragma unroll
    for (int p = 0; p < 4; p++) { s1[p] = ZERO; q1[p] = ZERO; }
#pragma unroll
    for (int i = 0; i < Hh; i++) {
        ulonglong2 wb = *(const ulonglong2*)&sw1b1[i][0];
#pragma unroll
        for (int p = 0; p < 4; p++) {
            u64 t; FMA2(t, xp[p], wb.x, wb.y);
            t = relu2(t);
            h[p][i] = t;
            ADD2(s1[p], s1[p], t);
            FMA2(q1[p], t, t, q1[p]);
        }
    }
    // LN1 in place
#pragma unroll
    for (int p = 0; p < 4; p++) {
        u64 mu, nmu, ex, var;
        MUL2(mu,  s1[p], c005);
        MUL2(nmu, s1[p], cn005);
        MUL2(ex,  q1[p], c005);
        FMA2(var, mu, nmu, ex);     // E[h^2] - mu^2 (biased)
        float2 vf = up(var);
        float rx = rsqrtf(vf.x + 1e-5f);
        float ry = rsqrtf(vf.y + 1e-5f);
        u64 r1 = pk(rx, ry);
        u64 v1; MUL2(v1, nmu, r1);
#pragma unroll
        for (int i = 0; i < Hh; i++)
            FMA2(h[p][i], h[p][i], r1, v1);
    }

    // ---- layer 2; accumulators start at b2; stream LN2 stats + W3 dot ----
    u64 s2[4], q2[4], d3[4];
#pragma unroll
    for (int p = 0; p < 4; p++) { s2[p] = ZERO; q2[p] = ZERO; d3[p] = ZERO; }

#pragma unroll 2
    for (int o = 0; o < Hh; o++) {
        const ulonglong2* wrow = (const ulonglong2*)&sw2f[o][0];
        ulonglong2 bw = *(const ulonglong2*)&sb2w3[o][0];   // {b2 dup, w3 dup}
        u64 a[4];
        a[0] = bw.x; a[1] = bw.x; a[2] = bw.x; a[3] = bw.x;
#pragma unroll
        for (int q = 0; q < Hh / 2; q++) {
            ulonglong2 wv = wrow[q];
#pragma unroll
            for (int p = 0; p < 4; p++) {
                FMA2(a[p], h[p][2 * q],     wv.x, a[p]);
                FMA2(a[p], h[p][2 * q + 1], wv.y, a[p]);
            }
        }
#pragma unroll
        for (int p = 0; p < 4; p++) {
            u64 h2 = relu2(a[p]);
            ADD2(s2[p], s2[p], h2);
            FMA2(q2[p], h2, h2, q2[p]);
            FMA2(d3[p], h2, bw.y, d3[p]);
        }
    }

    // ---- LN2 fold + head ----
    u64 w3s = *(const u64*)&sc[0];
    u64 b3d = *(const u64*)&sc[2];
    float outv[8];
#pragma unroll
    for (int p = 0; p < 4; p++) {
        u64 mu2, nmu2, ex2, var2;
        MUL2(mu2,  s2[p], c005);
        MUL2(nmu2, s2[p], cn005);
        MUL2(ex2,  q2[p], c005);
        FMA2(var2, mu2, nmu2, ex2);
        float2 vf = up(var2);
        float rx = rsqrtf(vf.x + 1e-5f);
        float ry = rsqrtf(vf.y + 1e-5f);
        u64 r2 = pk(rx, ry);
        u64 tmp; FMA2(tmp, nmu2, w3s, d3[p]);
        u64 o2;  FMA2(o2, r2, tmp, b3d);
        float2 of = up(o2);
        outv[2 * p] = of.x; outv[2 * p + 1] = of.y;
    }
    *(float4*)(tout + j0)     = make_float4(outv[0], outv[1], outv[2], outv[3]);
    *(float4*)(tout + j0 + 4) = make_float4(outv[4], outv[5], outv[6], outv[7]);
}

// ---------------------------------------------------------------------------
// Kernel 3: penalty (proven R9 form, PB=4). g_t is [k][n][t][b]: warp-load =
// one 512B (n,t) plane, 100% sector efficiency.
// prod_marginals underflows to exactly 0 in fp32, so d^2 = prod_joint^2.
// grid = 640 blocks, 128 threads (4 warps; warp = one dt).
// ---------------------------------------------------------------------------
#define PB 4

__global__ void __launch_bounds__(128) penalty_kernel(float* __restrict__ out) {
    int bid = blockIdx.x;            // 0..639
    int k   = bid >> 6;
    int tt0 = (bid & 63) * PB;

    __shared__ float s[64][132];     // [n*4+dt][b]
    __shared__ float sac[64][2];     // per col: {r, -mu*r}
    __shared__ float part[4];
    __shared__ unsigned int s_last;

    int tid = threadIdx.x;
    int wid = tid >> 5, lane = tid & 31;

    // load: warp-inst = one (n,dt) plane (32 lanes x float4 = 512B contiguous)
#pragma unroll
    for (int pp = 0; pp < 16; pp++) {
        int plane = pp * 4 + wid;            // = n*4 + dt
        int n  = plane >> 2;
        int dt = plane & 3;
        const float4* src = (const float4*)(g_t +
            ((size_t)(k * 16 + n)) * BT + (tt0 + dt) * 128);
        float4 v = src[lane];
        *(float4*)&s[plane][lane * 4] = v;
    }
    __syncthreads();

    // fused stats pass: sum + sumsq over b (2 threads per column)
    int col = tid >> 1, hf = tid & 1;
    float S = 0.f, Q = 0.f;
#pragma unroll 8
    for (int i = 0; i < 64; i++) {
        float v = s[col][hf * 64 + i];
        S += v; Q = fmaf(v, v, Q);
    }
    S += __shfl_xor_sync(0xffffffffu, S, 1);
    Q += __shfl_xor_sync(0xffffffffu, Q, 1);
    if (hf == 0) {
        float mu = S * (1.f / 128.f);
        float r  = 1.f / (sqrtf((Q - S * mu) * (1.f / 127.f)) + 1e-8f);
        sac[col][0] = r;
        sac[col][1] = -mu * r;
    }
    __syncthreads();

    // product pass: warp = dt; coefficients in registers (broadcast LDS)
    int dt = wid;
    float2 ac[16];
#pragma unroll
    for (int n = 0; n < 16; n++)
        ac[n] = *(const float2*)&sac[n * 4 + dt][0];

    float acc = 0.f;
#pragma unroll
    for (int j = 0; j < 4; j++) {
        int bb = lane + 32 * j;               // stride-1 lanes: conflict-free
        float prod = fmaf(s[0 * 4 + dt][bb], ac[0].x, ac[0].y);
#pragma unroll
        for (int n = 1; n < 16; n++)
            prod *= fmaf(s[n * 4 + dt][bb], ac[n].x, ac[n].y);
        acc += prod;
    }
#pragma unroll
    for (int o = 16; o; o >>= 1) acc += __shfl_xor_sync(0xffffffffu, acc, o);
    if (lane == 0) {
        float pj = acc * (1.f / 128.f);       // d = 0 - pj; d^2 = pj^2
        g_sq[k * Tt + tt0 + dt] = pj * pj;
    }

    // completion counter: last block reduces g_sq deterministically
    __threadfence();
    __syncthreads();
    if (tid == 0) {
        unsigned int t = atomicAdd(&g_ctr, 1u);
        s_last = (t == (unsigned int)(Kk * Tt / PB - 1)) ? 1u : 0u;
    }
    __syncthreads();
    if (s_last) {
        __threadfence();
        float facc = 0.f;
        for (int i = tid; i < KT; i += 128) facc += g_sq[i];
#pragma unroll
        for (int o = 16; o; o >>= 1) facc += __shfl_xor_sync(0xffffffffu, facc, o);
        if ((tid & 31) == 0) part[tid >> 5] = facc;
        __syncthreads();
        if (tid == 0) {
            out[0] = (part[0] + part[1] + part[2] + part[3]) * (1.f / (float)KT);
            g_ctr = 0u;   // reset for next graph replay
        }
    }
}

// ---------------------------------------------------------------------------
extern "C" void kernel_launch(void* const* d_in, const int* in_sizes, int n_in,
                              void* d_out, int out_size) {
    const float* x  = (const float*)d_in[0];
    const float* W1 = (const float*)d_in[1];
    const float* b1 = (const float*)d_in[2];
    const float* W2 = (const float*)d_in[3];
    const float* b2 = (const float*)d_in[4];
    const float* W3 = (const float*)d_in[5];
    const float* b3 = (const float*)d_in[6];

    std_kernel<<<128, 256>>>(x);

    dim3 g2(Kk * Nn, 32);
    mlp_kernel<<<g2, 128>>>(W1, b1, W2, b2, W3, b3);

    penalty_kernel<<<KT / PB, 128>>>((float*)d_out);
}